// round 11
// baseline (speedup 1.0000x reference)
#include <cuda_runtime.h>
#include <math.h>

// Problem constants
#define NN 4096
#define KK 8
#define DD 512
#define HH 512
#define G4 2048   // 4*H

// ---------------- static device scratch (no allocations allowed) ----------------
__device__ float g_WlhhT[HH * G4];     // [j][4e+gate] = Wl_hh[gate*512+e][j]
__device__ float g_WrhhT[HH * G4];
__device__ float g_WlihT[DD * G4];     // [k][4e+gate] = Wl_ih[gate*512+e][k]
__device__ float g_WrihT[DD * G4];
__device__ float g_WencT[2 * HH * DD]; // [j][e] = W_enc[e][j]
__device__ float g_biasL[G4];          // interleaved bih+bhh
__device__ float g_biasR[G4];
__device__ float g_AxL[NN * G4];       // x-term gate preactivations (incl. biases)
__device__ float g_AxR[NN * G4];
__device__ float g_AeL[NN * G4];       // enc-term gate preactivations (incl. biases)
__device__ float g_AeR[NN * G4];
__device__ int   g_ready[NN];
__device__ int   g_counter;

// ---------------- small helpers ----------------
__device__ __forceinline__ float sigf(float x) { return 1.0f / (1.0f + expf(-x)); }

__device__ __forceinline__ int ld_acquire(const int* p) {
    int v;
    asm volatile("ld.acquire.gpu.b32 %0, [%1];" : "=r"(v) : "l"(p) : "memory");
    return v;
}
__device__ __forceinline__ void st_release(int* p, int v) {
    asm volatile("st.release.gpu.b32 [%0], %1;" :: "l"(p), "r"(v) : "memory");
}
__device__ __forceinline__ void chain_bar(int chain) {
    asm volatile("bar.sync %0, %1;" :: "r"(chain + 1), "r"(512) : "memory");
}

// ---------------- reset ----------------
__global__ void reset_kernel() {
    int i = blockIdx.x * blockDim.x + threadIdx.x;
    if (i < NN) g_ready[i] = 0;
    if (i == 0) g_counter = 0;
}

// ---------------- preprocess: transpose + gate-interleave weights ----------------
__global__ void prep_kernel(const float* __restrict__ Wl_ih, const float* __restrict__ Wl_hh,
                            const float* __restrict__ Wr_ih, const float* __restrict__ Wr_hh,
                            const float* __restrict__ bl_ih, const float* __restrict__ bl_hh,
                            const float* __restrict__ br_ih, const float* __restrict__ br_hh,
                            const float* __restrict__ W_enc) {
    int idx = blockIdx.x * blockDim.x + threadIdx.x;
    int z = blockIdx.y;
    if (z < 4) {
        if (idx < 512 * 2048) {
            int j = idx >> 11, col = idx & 2047;
            int e = col >> 2, g = col & 3;
            const float* src = (z == 0) ? Wl_hh : (z == 1) ? Wr_hh : (z == 2) ? Wl_ih : Wr_ih;
            float* dst = (z == 0) ? g_WlhhT : (z == 1) ? g_WrhhT : (z == 2) ? g_WlihT : g_WrihT;
            dst[idx] = src[(g * 512 + e) * 512 + j];
        }
    } else {
        if (idx < 1024 * 512) {
            int j = idx >> 9, e = idx & 511;
            g_WencT[idx] = W_enc[e * 1024 + j];
        }
        if (idx < 2048) {
            int e = idx >> 2, g = idx & 3;
            int r = g * 512 + e;
            g_biasL[idx] = bl_ih[r] + bl_hh[r];
            g_biasR[idx] = br_ih[r] + br_hh[r];
        }
    }
}

// ---------------- batched GEMM: Ax = x0 @ WihT_int + bias  ([4096,512]x[512,2048]) ----------------
#define BM 128
#define BN 128
#define BK 8
__global__ __launch_bounds__(256) void gemm_ax(const float* __restrict__ x0) {
    int z = blockIdx.z;
    const float* B = z ? g_WrihT : g_WlihT;
    const float* bias = z ? g_biasR : g_biasL;
    float* C = z ? g_AxR : g_AxL;
    int n0 = blockIdx.x * BN;   // over 2048
    int m0 = blockIdx.y * BM;   // over 4096

    __shared__ float As[BK][BM + 4];
    __shared__ float Bs[BK][BN];

    float acc[8][8];
#pragma unroll
    for (int i = 0; i < 8; i++)
#pragma unroll
        for (int j = 0; j < 8; j++) acc[i][j] = 0.0f;

    int u = threadIdx.x;
    int tm = (u >> 4) * 8;
    int tn = (u & 15) * 8;

    for (int k0 = 0; k0 < 512; k0 += BK) {
        {
            int row = u >> 1, kk = (u & 1) * 4;
            float4 a4 = *(const float4*)&x0[(m0 + row) * 512 + k0 + kk];
            As[kk + 0][row] = a4.x; As[kk + 1][row] = a4.y;
            As[kk + 2][row] = a4.z; As[kk + 3][row] = a4.w;
        }
        {
            int kb = u >> 5, cc = (u & 31) * 4;
            *(float4*)&Bs[kb][cc] = *(const float4*)&B[(k0 + kb) * 2048 + n0 + cc];
        }
        __syncthreads();
#pragma unroll
        for (int k = 0; k < BK; k++) {
            float a[8], b[8];
            *(float4*)(a)     = *(float4*)&As[k][tm];
            *(float4*)(a + 4) = *(float4*)&As[k][tm + 4];
            *(float4*)(b)     = *(float4*)&Bs[k][tn];
            *(float4*)(b + 4) = *(float4*)&Bs[k][tn + 4];
#pragma unroll
            for (int i = 0; i < 8; i++)
#pragma unroll
                for (int j = 0; j < 8; j++) acc[i][j] += a[i] * b[j];
        }
        __syncthreads();
    }
#pragma unroll
    for (int i = 0; i < 8; i++) {
#pragma unroll
        for (int j = 0; j < 8; j += 4) {
            float4 o;
            o.x = acc[i][j + 0] + bias[n0 + tn + j + 0];
            o.y = acc[i][j + 1] + bias[n0 + tn + j + 1];
            o.z = acc[i][j + 2] + bias[n0 + tn + j + 2];
            o.w = acc[i][j + 3] + bias[n0 + tn + j + 3];
            *(float4*)&C[(m0 + tm + i) * 2048 + n0 + tn + j] = o;
        }
    }
}

// ---------------- persistent tree kernel ----------------
__global__ void __launch_bounds__(1024, 1) tree_kernel(
    const int* __restrict__ lch, const int* __restrict__ rch, int chstride,
    const float* __restrict__ b_enc, float* __restrict__ out) {

    __shared__ float sh_hL[512];
    __shared__ float sh_hR[512];
    __shared__ float sh_enc[512];
    __shared__ float sh_part[1024];
    __shared__ float sh_benc[512];
    __shared__ int   s_ch[16];
    __shared__ int   s_node;

    int tid = threadIdx.x;
    int chain = tid >> 9;        // 0 = left, 1 = right
    int t = tid & 511;

    if (tid < 512) sh_benc[tid] = b_enc[tid];

    const float4* Whq   = (const float4*)(chain ? g_WrhhT : g_WlhhT);
    const float4* Wiq   = (const float4*)(chain ? g_WrihT : g_WlihT);
    const float4* Axq   = (const float4*)(chain ? g_AxR : g_AxL);
    const float4* Aeq   = (const float4*)(chain ? g_AeR : g_AeL);
    float4*       AeOut = (float4*)(chain ? g_AeR : g_AeL);
    const float4* biasq = (const float4*)(chain ? g_biasR : g_biasL);
    float* sh_h = chain ? sh_hR : sh_hL;

    while (true) {
        __syncthreads();
        if (tid == 0) s_node = atomicAdd(&g_counter, 1);
        __syncthreads();
        int i = s_node;
        if (i >= NN) break;

        // stage children into shared (stride handles int32 or int64 input)
        if (tid < 8)        s_ch[tid] = lch[(i * 8 + tid) * chstride];
        else if (tid < 16)  s_ch[tid] = rch[(i * 8 + (tid - 8)) * chstride];
        __syncthreads();

        // wait for all children to be ready
        if (tid < 16) {
            int c = s_ch[tid];
            if (c >= 0) {
                while (ld_acquire(&g_ready[c]) == 0) { __nanosleep(64); }
            }
        }
        __syncthreads();

        // -------- chain LSTM (both chains run concurrently in half-blocks) --------
        // step 0: h=c=0 -> g = Ax (biases folded in)
        float cc;
        {
            float4 g4 = Axq[i * 512 + t];
            float ig = sigf(g4.x);
            float gg = tanhf(g4.z);
            cc = ig * gg;                       // f*0 + i*tanh(g)
            float oo = sigf(g4.w);
            sh_h[t] = oo * tanhf(cc);
        }
        chain_bar(chain);

        const int* mych = &s_ch[chain * 8];
        for (int k = 0; k < 8; k++) {
            int cj = mych[k];
            if (cj < 0) break;

            // acc = h @ Whh^T (gate-interleaved columns 4t..4t+3)
            float4 acc; acc.x = acc.y = acc.z = acc.w = 0.0f;
            const float4* hq = (const float4*)sh_h;
#pragma unroll 2
            for (int j4 = 0; j4 < 128; j4++) {
                float4 h4 = hq[j4];
                const float4* wp = Whq + (j4 * 4) * 512 + t;
                float4 w0 = wp[0];
                float4 w1 = wp[512];
                float4 w2 = wp[1024];
                float4 w3 = wp[1536];
                acc.x += w0.x * h4.x + w1.x * h4.y + w2.x * h4.z + w3.x * h4.w;
                acc.y += w0.y * h4.x + w1.y * h4.y + w2.y * h4.z + w3.y * h4.w;
                acc.z += w0.z * h4.x + w1.z * h4.y + w2.z * h4.z + w3.z * h4.w;
                acc.w += w0.w * h4.x + w1.w * h4.y + w2.w * h4.z + w3.w * h4.w;
            }
            float4 a4 = Aeq[cj * 512 + t];
            float ig = sigf(acc.x + a4.x);
            float ff = sigf(acc.y + a4.y);
            float gg = tanhf(acc.z + a4.z);
            float oo = sigf(acc.w + a4.w);
            cc = ff * cc + ig * gg;
            float hh = oo * tanhf(cc);
            chain_bar(chain);       // all reads of sh_h done
            sh_h[t] = hh;
            chain_bar(chain);       // writes visible to whole chain
        }
        __syncthreads();            // both chains done

        // -------- encoder: enc = tanh(Wenc @ [hl;hr] + b_enc) --------
        {
            float accp = 0.0f;
            const float* srch = chain ? sh_hR : sh_hL;
            const float* Wt = g_WencT + (chain * 512) * 512;
            for (int j = 0; j < 512; j++)
                accp += Wt[j * 512 + t] * srch[j];
            sh_part[tid] = accp;
        }
        __syncthreads();
        if (tid < 512) {
            float e = tanhf(sh_part[tid] + sh_part[512 + tid] + sh_benc[tid]);
            sh_enc[tid] = e;
            out[i * 512 + tid] = e;
        }
        __syncthreads();

        // -------- produce Ae for parents: Wih @ enc + biases --------
        {
            float4 acc = biasq[t];
            const float4* eq = (const float4*)sh_enc;
#pragma unroll 2
            for (int j4 = 0; j4 < 128; j4++) {
                float4 e4 = eq[j4];
                const float4* wp = Wiq + (j4 * 4) * 512 + t;
                float4 w0 = wp[0];
                float4 w1 = wp[512];
                float4 w2 = wp[1024];
                float4 w3 = wp[1536];
                acc.x += w0.x * e4.x + w1.x * e4.y + w2.x * e4.z + w3.x * e4.w;
                acc.y += w0.y * e4.x + w1.y * e4.y + w2.y * e4.z + w3.y * e4.w;
                acc.z += w0.z * e4.x + w1.z * e4.y + w2.z * e4.z + w3.z * e4.w;
                acc.w += w0.w * e4.x + w1.w * e4.y + w2.w * e4.z + w3.w * e4.w;
            }
            AeOut[i * 512 + t] = acc;
        }
        __threadfence();
        __syncthreads();
        if (tid == 0) st_release(&g_ready[i], 1);
    }
}

// ---------------- launch ----------------
extern "C" void kernel_launch(void* const* d_in, const int* in_sizes, int n_in,
                              void* d_out, int out_size) {
    const float* x0    = (const float*)d_in[0];
    const float* Wl_ih = (const float*)d_in[1];
    const float* Wl_hh = (const float*)d_in[2];
    const float* bl_ih = (const float*)d_in[3];
    const float* bl_hh = (const float*)d_in[4];
    const float* Wr_ih = (const float*)d_in[5];
    const float* Wr_hh = (const float*)d_in[6];
    const float* br_ih = (const float*)d_in[7];
    const float* br_hh = (const float*)d_in[8];
    const float* W_enc = (const float*)d_in[9];
    const float* b_enc = (const float*)d_in[10];
    const int*   lch   = (const int*)d_in[11];
    const int*   rch   = (const int*)d_in[12];
    float* out = (float*)d_out;

    // children may be serialized as int32 (stride 1) or int64 (stride 2, LE low word)
    int chstride = in_sizes[11] / (NN * KK);
    if (chstride < 1) chstride = 1;

    reset_kernel<<<16, 256>>>();

    dim3 pgrid((512 * 2048 + 255) / 256, 5);
    prep_kernel<<<pgrid, 256>>>(Wl_ih, Wl_hh, Wr_ih, Wr_hh,
                                bl_ih, bl_hh, br_ih, br_hh, W_enc);

    dim3 ggrid(2048 / BN, NN / BM, 2);
    gemm_ax<<<ggrid, 256>>>(x0);

    int sm = 148;
    cudaDeviceGetAttribute(&sm, cudaDevAttrMultiProcessorCount, 0);
    tree_kernel<<<sm, 1024>>>(lch, rch, chstride, b_enc, out);
}